// round 10
// baseline (speedup 1.0000x reference)
#include <cuda_runtime.h>
#include <cuda_bf16.h>
#include <cstdint>
#include <cstddef>

// ---------------- constants ----------------
#define NWIN   2048
#define NTOK   64
#define CDIM   128
#define NHEAD  4
#define HDIM   32
#define IMGH   256
#define IMGW   256
#define NB     2
#define KCONV  1152          // 9*128

// ---------------- scratch ----------------
// q, v: [win][head][tok][32] bf16 hi/lo.  k, kref: TRANSPOSED [win][head][ch][64].
__device__ __align__(16) __nv_bfloat16 g_qh [NWIN*NHEAD*NTOK*HDIM];
__device__ __align__(16) __nv_bfloat16 g_ql [NWIN*NHEAD*NTOK*HDIM];
__device__ __align__(16) __nv_bfloat16 g_kh [NWIN*NHEAD*NTOK*HDIM];
__device__ __align__(16) __nv_bfloat16 g_kl [NWIN*NHEAD*NTOK*HDIM];
__device__ __align__(16) __nv_bfloat16 g_krh[NWIN*NHEAD*NTOK*HDIM];
__device__ __align__(16) __nv_bfloat16 g_krl[NWIN*NHEAD*NTOK*HDIM];
__device__ __align__(16) __nv_bfloat16 g_vh [NWIN*NHEAD*NTOK*HDIM];
__device__ __align__(16) __nv_bfloat16 g_vl [NWIN*NHEAD*NTOK*HDIM];
__device__ float g_imgA[(size_t)NB*IMGH*IMGW*CDIM];
__device__ float g_imgB[(size_t)NB*IMGH*IMGW*CDIM];
__device__ float g_imgC[(size_t)NB*IMGH*IMGW*CDIM];
__device__ __nv_bfloat16 g_wbf_hi[4*KCONV*128];   // conv weights [conv][k][o]
__device__ __nv_bfloat16 g_wbf_lo[4*KCONV*128];
__device__ __nv_bfloat16 g_wqkv_hi[128*384];      // [k][o]
__device__ __nv_bfloat16 g_wqkv_lo[128*384];
__device__ __nv_bfloat16 g_wproj_hi[128*128];     // [k][o]
__device__ __nv_bfloat16 g_wproj_lo[128*128];

// ---------------- weight prep ----------------
__global__ void prep_weights(const float* __restrict__ qkv_w,
                             const float* __restrict__ proj_w) {
    int t = blockIdx.x * blockDim.x + threadIdx.x;   // 0..49151
    if (t < 384*128) {
        int o = t / 128, k = t % 128;
        float x = qkv_w[t];
        __nv_bfloat16 hi = __float2bfloat16(x);
        g_wqkv_hi[k*384 + o] = hi;
        g_wqkv_lo[k*384 + o] = __float2bfloat16(x - __bfloat162float(hi));
    }
    if (t < 128*128) {
        int o = t / 128, k = t % 128;
        float x = proj_w[t];
        __nv_bfloat16 hi = __float2bfloat16(x);
        g_wproj_hi[k*128 + o] = hi;
        g_wproj_lo[k*128 + o] = __float2bfloat16(x - __bfloat162float(hi));
    }
}

__global__ void split_weights(const float* __restrict__ w0, const float* __restrict__ w1,
                              const float* __restrict__ w2, const float* __restrict__ w3) {
    int t = blockIdx.x * blockDim.x + threadIdx.x;
    if (t >= KCONV*128) return;
    const float* ws[4] = {w0, w1, w2, w3};
    #pragma unroll
    for (int c = 0; c < 4; c++) {
        float x = ws[c][t];
        __nv_bfloat16 hi = __float2bfloat16(x);
        float lo = x - __bfloat162float(hi);
        g_wbf_hi[c*KCONV*128 + t] = hi;
        g_wbf_lo[c*KCONV*128 + t] = __float2bfloat16(lo);
    }
}

// ---------------- mma helpers ----------------
__device__ __forceinline__ void ldsm4(uint32_t* r, uint32_t addr) {
    asm volatile("ldmatrix.sync.aligned.m8n8.x4.shared.b16 {%0,%1,%2,%3}, [%4];"
        : "=r"(r[0]), "=r"(r[1]), "=r"(r[2]), "=r"(r[3]) : "r"(addr));
}
__device__ __forceinline__ void ldsm4t(uint32_t* r, uint32_t addr) {
    asm volatile("ldmatrix.sync.aligned.m8n8.x4.trans.shared.b16 {%0,%1,%2,%3}, [%4];"
        : "=r"(r[0]), "=r"(r[1]), "=r"(r[2]), "=r"(r[3]) : "r"(addr));
}
__device__ __forceinline__ void mma16816(float* c, const uint32_t* a, const uint32_t* b) {
    asm volatile("mma.sync.aligned.m16n8k16.row.col.f32.bf16.bf16.f32 "
        "{%0,%1,%2,%3}, {%4,%5,%6,%7}, {%8,%9}, {%0,%1,%2,%3};"
        : "+f"(c[0]), "+f"(c[1]), "+f"(c[2]), "+f"(c[3])
        : "r"(a[0]), "r"(a[1]), "r"(a[2]), "r"(a[3]), "r"(b[0]), "r"(b[1]));
}
__device__ __forceinline__ void cp_async16(uint32_t dst, const void* src) {
    asm volatile("cp.async.cg.shared.global [%0], [%1], 16;" :: "r"(dst), "l"(src));
}
__device__ __forceinline__ void split_store(__nv_bfloat16* hiP, __nv_bfloat16* loP,
                                            int off, float4 v) {
    __nv_bfloat16 hx = __float2bfloat16(v.x), hy = __float2bfloat16(v.y);
    __nv_bfloat16 hz = __float2bfloat16(v.z), hw = __float2bfloat16(v.w);
    uint32_t h01 = ((uint32_t)__bfloat16_as_ushort(hy) << 16) | __bfloat16_as_ushort(hx);
    uint32_t h23 = ((uint32_t)__bfloat16_as_ushort(hw) << 16) | __bfloat16_as_ushort(hz);
    __nv_bfloat16 l0 = __float2bfloat16(v.x - __bfloat162float(hx));
    __nv_bfloat16 l1 = __float2bfloat16(v.y - __bfloat162float(hy));
    __nv_bfloat16 l2 = __float2bfloat16(v.z - __bfloat162float(hz));
    __nv_bfloat16 l3 = __float2bfloat16(v.w - __bfloat162float(hw));
    uint32_t lo01 = ((uint32_t)__bfloat16_as_ushort(l1) << 16) | __bfloat16_as_ushort(l0);
    uint32_t lo23 = ((uint32_t)__bfloat16_as_ushort(l3) << 16) | __bfloat16_as_ushort(l2);
    *(uint32_t*)(hiP + off)     = h01;
    *(uint32_t*)(hiP + off + 2) = h23;
    *(uint32_t*)(loP + off)     = lo01;
    *(uint32_t*)(loP + off + 2) = lo23;
}
__device__ __forceinline__ void st_pair(__nv_bfloat16* hp, __nv_bfloat16* lp,
                                        float x0, float x1) {
    __nv_bfloat16 h0 = __float2bfloat16(x0), h1 = __float2bfloat16(x1);
    *(__nv_bfloat162*)hp = __halves2bfloat162(h0, h1);
    *(__nv_bfloat162*)lp = __halves2bfloat162(
        __float2bfloat16(x0 - __bfloat162float(h0)),
        __float2bfloat16(x1 - __bfloat162float(h1)));
}
__device__ __forceinline__ void stage_bf16(__nv_bfloat16* hP, __nv_bfloat16* lP,
                                           int off, float x) {
    __nv_bfloat16 h = __float2bfloat16(x);
    hP[off] = h;
    lP[off] = __float2bfloat16(x - __bfloat162float(h));
}

// ================= fused QKV (x branch): GEMM 64x384x128 + per-head norm =================
#define QKV_SMEM 84992
__global__ __launch_bounds__(256) void qkv_mma(
    const float* __restrict__ src, const float* __restrict__ qkv_b)
{
    extern __shared__ __align__(16) unsigned char smem_raw[];
    __nv_bfloat16* aHiP = reinterpret_cast<__nv_bfloat16*>(smem_raw);
    __nv_bfloat16* aLoP = aHiP + 64*136;
    const uint32_t smem_u = (uint32_t)__cvta_generic_to_shared(smem_raw);
    const uint32_t aHiU = smem_u, aLoU = smem_u + 17408, bU = smem_u + 34816;

    const int t = threadIdx.x, lane = t & 31, wid = t >> 5;
    const int warpM = wid >> 2, warpN = wid & 3;   // 2 x 4, warp tile 32 x 96
    const int win = blockIdx.x;
    const float* srcw = src + (size_t)win * NTOK * CDIM;

    for (int idx = t; idx < 2048; idx += 256) {
        int r = idx >> 5, c4 = idx & 31;
        float4 v = *(const float4*)(srcw + r*128 + c4*4);
        split_store(aHiP, aLoP, r*136 + c4*4, v);
    }

    auto prefetchB = [&](int ks, int stage) {
        #pragma unroll
        for (int i = 0; i < 6; i++) {
            int c = t + i*256;
            int part = c >= 768; int cc = c - part*768;
            int row = cc / 48, seg = cc % 48;
            const __nv_bfloat16* sp = (part ? g_wqkv_lo : g_wqkv_hi) + (ks*16 + row)*384 + seg*8;
            cp_async16(bU + stage*25088 + part*12544 + row*784 + seg*16, sp);
        }
    };
    prefetchB(0, 0);
    asm volatile("cp.async.commit_group;");
    __syncthreads();

    float acc[2][12][4];
    #pragma unroll
    for (int mi = 0; mi < 2; mi++)
        #pragma unroll
        for (int ni = 0; ni < 12; ni++)
            #pragma unroll
            for (int e = 0; e < 4; e++) acc[mi][ni][e] = 0.f;

    for (int ks = 0; ks < 8; ks++) {
        const int stage = ks & 1;
        if (ks < 7) {
            prefetchB(ks + 1, stage ^ 1);
            asm volatile("cp.async.commit_group;");
            asm volatile("cp.async.wait_group 1;");
        } else {
            asm volatile("cp.async.wait_group 0;");
        }
        __syncthreads();

        const int kc = ks * 16;
        uint32_t a_hi[2][4], a_lo[2][4];
        #pragma unroll
        for (int mi = 0; mi < 2; mi++) {
            int row = warpM*32 + mi*16 + (lane & 15);
            uint32_t off = (uint32_t)(row*272 + (kc + ((lane >> 4) << 3))*2);
            ldsm4(a_hi[mi], aHiU + off);
            ldsm4(a_lo[mi], aLoU + off);
        }
        const uint32_t bst = bU + stage*25088;
        #pragma unroll
        for (int pair = 0; pair < 6; pair++) {
            uint32_t off = (uint32_t)((lane & 15)*784 +
                           (warpN*96 + pair*16 + ((lane >> 4) << 3))*2);
            uint32_t bh[4], bl[4];
            ldsm4t(bh, bst + off);
            ldsm4t(bl, bst + 12544 + off);
            #pragma unroll
            for (int mi = 0; mi < 2; mi++) {
                mma16816(acc[mi][2*pair],   a_hi[mi], bh);
                mma16816(acc[mi][2*pair],   a_hi[mi], bl);
                mma16816(acc[mi][2*pair],   a_lo[mi], bh);
                mma16816(acc[mi][2*pair+1], a_hi[mi], bh+2);
                mma16816(acc[mi][2*pair+1], a_hi[mi], bl+2);
                mma16816(acc[mi][2*pair+1], a_lo[mi], bh+2);
            }
        }
        __syncthreads();
    }

    // epilogue: bias, per-head L2 norm (q,k); q,v direct; k staged to smem (A area free)
    #pragma unroll
    for (int mi = 0; mi < 2; mi++) {
        int row0 = warpM*32 + mi*16 + (lane >> 2);
        int row1 = row0 + 8;
        #pragma unroll
        for (int ni = 0; ni < 12; ni++) {
            int col = warpN*96 + ni*8 + (lane & 3)*2;
            float2 bb = *(const float2*)(qkv_b + col);
            acc[mi][ni][0] += bb.x; acc[mi][ni][1] += bb.y;
            acc[mi][ni][2] += bb.x; acc[mi][ni][3] += bb.y;
        }
        #pragma unroll
        for (int sg = 0; sg < 3; sg++) {
            float s0 = 0.f, s1 = 0.f;
            #pragma unroll
            for (int k = 0; k < 4; k++) {
                int ni = sg*4 + k;
                s0 += acc[mi][ni][0]*acc[mi][ni][0] + acc[mi][ni][1]*acc[mi][ni][1];
                s1 += acc[mi][ni][2]*acc[mi][ni][2] + acc[mi][ni][3]*acc[mi][ni][3];
            }
            s0 += __shfl_xor_sync(0xffffffffu, s0, 1);
            s0 += __shfl_xor_sync(0xffffffffu, s0, 2);
            s1 += __shfl_xor_sync(0xffffffffu, s1, 1);
            s1 += __shfl_xor_sync(0xffffffffu, s1, 2);
            int gcol = warpN*96 + sg*32;
            int sec = gcol >> 7, head = (gcol >> 5) & 3;
            float sc0 = 1.f, sc1 = 1.f;
            if (sec < 2) {
                sc0 = 1.f / fmaxf(sqrtf(s0), 1e-12f);
                sc1 = 1.f / fmaxf(sqrtf(s1), 1e-12f);
            }
            const size_t base = (size_t)(win*4 + head) * 2048;
            #pragma unroll
            for (int k = 0; k < 4; k++) {
                int ni = sg*4 + k;
                int d = k*8 + (lane & 3)*2;
                float x0 = acc[mi][ni][0]*sc0, x1 = acc[mi][ni][1]*sc0;
                float x2 = acc[mi][ni][2]*sc1, x3 = acc[mi][ni][3]*sc1;
                if (sec == 0) {
                    st_pair(g_qh + base + row0*32 + d, g_ql + base + row0*32 + d, x0, x1);
                    st_pair(g_qh + base + row1*32 + d, g_ql + base + row1*32 + d, x2, x3);
                } else if (sec == 2) {
                    st_pair(g_vh + base + row0*32 + d, g_vl + base + row0*32 + d, x0, x1);
                    st_pair(g_vh + base + row1*32 + d, g_vl + base + row1*32 + d, x2, x3);
                } else {
                    // k: stage transposed [ch 0..127][tok 0..63] into A smem area
                    int ch = (gcol - 128) + d;
                    stage_bf16(aHiP, aLoP, ch*64 + row0, x0);
                    stage_bf16(aHiP, aLoP, (ch+1)*64 + row0, x1);
                    stage_bf16(aHiP, aLoP, ch*64 + row1, x2);
                    stage_bf16(aHiP, aLoP, (ch+1)*64 + row1, x3);
                }
            }
        }
    }
    __syncthreads();

    // coalesced copy-out: [head][ch][tok] is contiguous = win*8192 + ch*64 + tok
    {
        __nv_bfloat16* dh = g_kh + (size_t)win*8192;
        __nv_bfloat16* dl = g_kl + (size_t)win*8192;
        #pragma unroll
        for (int i = 0; i < 4; i++) {
            int idx = t + i*256;           // 0..1023 float4 chunks
            int off = idx*8;               // bf16 offset
            *(float4*)(dh + off) = *(const float4*)(aHiP + off);
            *(float4*)(dl + off) = *(const float4*)(aLoP + off);
        }
    }
}

// ================= k_ref: GEMM 64x128x128 + norm, staged transposed out =================
#define KREF_SMEM 52224
__global__ __launch_bounds__(256) void kref_mma(
    const float* __restrict__ src, const float* __restrict__ qkv_b)
{
    extern __shared__ __align__(16) unsigned char smem_raw[];
    __nv_bfloat16* aHiP = reinterpret_cast<__nv_bfloat16*>(smem_raw);
    __nv_bfloat16* aLoP = aHiP + 64*136;
    const uint32_t smem_u = (uint32_t)__cvta_generic_to_shared(smem_raw);
    const uint32_t aHiU = smem_u, aLoU = smem_u + 17408, bU = smem_u + 34816;

    const int t = threadIdx.x, lane = t & 31, wid = t >> 5;
    const int warpM = wid >> 2, warpN = wid & 3;
    const int win = blockIdx.x;
    const float* srcw = src + (size_t)win * NTOK * CDIM;

    for (int idx = t; idx < 2048; idx += 256) {
        int r = idx >> 5, c4 = idx & 31;
        float4 v = *(const float4*)(srcw + r*128 + c4*4);
        split_store(aHiP, aLoP, r*136 + c4*4, v);
    }

    auto prefetchB = [&](int ks, int stage) {
        #pragma unroll
        for (int i = 0; i < 2; i++) {
            int c = t + i*256;
            int part = c >= 256; int cc = c - part*256;
            int row = cc >> 4, seg = cc & 15;
            const __nv_bfloat16* sp = (part ? g_wqkv_lo : g_wqkv_hi) + (ks*16 + row)*384 + 128 + seg*8;
            cp_async16(bU + stage*8704 + part*4352 + row*272 + seg*16, sp);
        }
    };
    prefetchB(0, 0);
    asm volatile("cp.async.commit_group;");
    __syncthreads();

    float acc[2][4][4];
    #pragma unroll
    for (int mi = 0; mi < 2; mi++)
        #pragma unroll
        for (int ni = 0; ni < 4; ni++)
            #pragma unroll
            for (int e = 0; e < 4; e++) acc[mi][ni][e] = 0.f;

    for (int ks = 0; ks < 8; ks++) {
        const int stage = ks & 1;
        if (ks < 7) {
            prefetchB(ks + 1, stage ^ 1);
            asm volatile("cp.async.commit_group;");
            asm volatile("cp.async.wait_group 1;");
        } else {
            asm volatile("cp.async.wait_group 0;");
        }
        __syncthreads();

        const int kc = ks * 16;
        uint32_t a_hi[2][4], a_lo[2][4];
        #pragma unroll
        for (int mi = 0; mi < 2; mi++) {
            int row = warpM*32 + mi*16 + (lane & 15);
            uint32_t off = (uint32_t)(row*272 + (kc + ((lane >> 4) << 3))*2);
            ldsm4(a_hi[mi], aHiU + off);
            ldsm4(a_lo[mi], aLoU + off);
        }
        const uint32_t bst = bU + stage*8704;
        #pragma unroll
        for (int pair = 0; pair < 2; pair++) {
            uint32_t off = (uint32_t)((lane & 15)*272 +
                           (warpN*32 + pair*16 + ((lane >> 4) << 3))*2);
            uint32_t bh[4], bl[4];
            ldsm4t(bh, bst + off);
            ldsm4t(bl, bst + 4352 + off);
            #pragma unroll
            for (int mi = 0; mi < 2; mi++) {
                mma16816(acc[mi][2*pair],   a_hi[mi], bh);
                mma16816(acc[mi][2*pair],   a_hi[mi], bl);
                mma16816(acc[mi][2*pair],   a_lo[mi], bh);
                mma16816(acc[mi][2*pair+1], a_hi[mi], bh+2);
                mma16816(acc[mi][2*pair+1], a_hi[mi], bl+2);
                mma16816(acc[mi][2*pair+1], a_lo[mi], bh+2);
            }
        }
        __syncthreads();
    }

    #pragma unroll
    for (int mi = 0; mi < 2; mi++) {
        int row0 = warpM*32 + mi*16 + (lane >> 2);
        int row1 = row0 + 8;
        #pragma unroll
        for (int ni = 0; ni < 4; ni++) {
            int col = warpN*32 + ni*8 + (lane & 3)*2;
            float2 bb = *(const float2*)(qkv_b + 128 + col);
            acc[mi][ni][0] += bb.x; acc[mi][ni][1] += bb.y;
            acc[mi][ni][2] += bb.x; acc[mi][ni][3] += bb.y;
        }
        float s0 = 0.f, s1 = 0.f;
        #pragma unroll
        for (int ni = 0; ni < 4; ni++) {
            s0 += acc[mi][ni][0]*acc[mi][ni][0] + acc[mi][ni][1]*acc[mi][ni][1];
            s1 += acc[mi][ni][2]*acc[mi][ni][2] + acc[mi][ni][3]*acc[mi][ni][3];
        }
        s0 += __shfl_xor_sync(0xffffffffu, s0, 1);
        s0 += __shfl_xor_sync(0xffffffffu, s0, 2);
        s1 += __shfl_xor_sync(0xffffffffu, s1, 1);
        s1 += __shfl_xor_sync(0xffffffffu, s1, 2);
        float sc0 = 1.f / fmaxf(sqrtf(s0), 1e-12f);
        float sc1 = 1.f / fmaxf(sqrtf(s1), 1e-12f);
        #pragma unroll
        for (int ni = 0; ni < 4; ni++) {
            int ch = warpN*32 + ni*8 + (lane & 3)*2;   // global ch 0..127
            float x0 = acc[mi][ni][0]*sc0, x1 = acc[mi][ni][1]*sc0;
            float x2 = acc[mi][ni][2]*sc1, x3 = acc[mi][ni][3]*sc1;
            stage_bf16(aHiP, aLoP, ch*64 + row0, x0);
            stage_bf16(aHiP, aLoP, (ch+1)*64 + row0, x1);
            stage_bf16(aHiP, aLoP, ch*64 + row1, x2);
            stage_bf16(aHiP, aLoP, (ch+1)*64 + row1, x3);
        }
    }
    __syncthreads();

    {
        __nv_bfloat16* dh = g_krh + (size_t)win*8192;
        __nv_bfloat16* dl = g_krl + (size_t)win*8192;
        #pragma unroll
        for (int i = 0; i < 4; i++) {
            int idx = t + i*256;
            int off = idx*8;
            *(float4*)(dh + off) = *(const float4*)(aHiP + off);
            *(float4*)(dl + off) = *(const float4*)(aLoP + off);
        }
    }
}

// ---------------- attention: tensor-core scores + AV (unchanged from R7) ----------------
#define sQH 0
#define sQL 5120
#define sKH 10240
#define sKL 14848
#define sRH 19456
#define sRL 24064
#define sVH 28672
#define sVL 33792
#define sPH 38912
#define sPL 48128
#define sS1 57344
#define sS2 74752
#define sBIAS 92160
#define sSUM 95760
#define ATTN_SMEM_BYTES 96512
#define SPITCH 68

__global__ __launch_bounds__(256) void attn_mma(
    const float* __restrict__ rel_bias, const float* __restrict__ logit_scale,
    const float* __restrict__ gating)
{
    extern __shared__ __align__(16) unsigned char smem_raw[];
    const uint32_t su = (uint32_t)__cvta_generic_to_shared(smem_raw);
    float* S1    = (float*)(smem_raw + sS1);
    float* S2    = (float*)(smem_raw + sS2);
    float* sbias = (float*)(smem_raw + sBIAS);
    float* ssum1 = (float*)(smem_raw + sSUM);
    float* ssum2 = ssum1 + 64;
    __nv_bfloat16* PH = (__nv_bfloat16*)(smem_raw + sPH);
    __nv_bfloat16* PL = (__nv_bfloat16*)(smem_raw + sPL);

    const int t = threadIdx.x, lane = t & 31, wid = t >> 5;
    const int win = blockIdx.x;
    const int b   = win >> 10;
    const int hw  = (win & 1023) >> 5;
    const int ww  = win & 31;

    for (int i = t; i < 900; i += 256) sbias[i] = rel_bias[i];

    for (int head = 0; head < 4; head++) {
        float ls = __expf(fminf(logit_scale[head], 4.6051702f));
        float gt = 1.f / (1.f + __expf(-gating[head]));
        const size_t base = (size_t)(win*4 + head) * 2048;

        {
            int rq = t >> 2, cq = t & 3;
            cp_async16(su + sQH + rq*80 + cq*16, g_qh + base + rq*32 + cq*8);
            cp_async16(su + sQL + rq*80 + cq*16, g_ql + base + rq*32 + cq*8);
            cp_async16(su + sVH + rq*80 + cq*16, g_vh + base + rq*32 + cq*8);
            cp_async16(su + sVL + rq*80 + cq*16, g_vl + base + rq*32 + cq*8);
            int rk = t >> 3, ck = t & 7;
            cp_async16(su + sKH + rk*144 + ck*16, g_kh  + base + rk*64 + ck*8);
            cp_async16(su + sKL + rk*144 + ck*16, g_kl  + base + rk*64 + ck*8);
            cp_async16(su + sRH + rk*144 + ck*16, g_krh + base + rk*64 + ck*8);
            cp_async16(su + sRL + rk*144 + ck*16, g_krl + base + rk*64 + ck*8);
        }
        asm volatile("cp.async.commit_group;");
        asm volatile("cp.async.wait_group 0;");
        __syncthreads();

        {
            const int mat = wid >> 2;
            const int nbase = (wid & 3) * 16;
            const uint32_t bHu = su + (mat ? sRH : sKH);
            const uint32_t bLu = su + (mat ? sRL : sKL);
            float* Sx = mat ? S2 : S1;

            uint32_t bh[2][4], bl[2][4];
            #pragma unroll
            for (int ks = 0; ks < 2; ks++) {
                uint32_t off = (uint32_t)((ks*16 + (lane & 15))*144 +
                               (nbase + ((lane >> 4) << 3))*2);
                ldsm4t(bh[ks], bHu + off);
                ldsm4t(bl[ks], bLu + off);
            }
            #pragma unroll
            for (int mi = 0; mi < 4; mi++) {
                uint32_t ah[2][4], al[2][4];
                #pragma unroll
                for (int ks = 0; ks < 2; ks++) {
                    uint32_t off = (uint32_t)((mi*16 + (lane & 15))*80 +
                                   (ks*16 + ((lane >> 4) << 3))*2);
                    ldsm4(ah[ks], su + sQH + off);
                    ldsm4(al[ks], su + sQL + off);
                }
                float acc[2][4];
                #pragma unroll
                for (int nj = 0; nj < 2; nj++)
                    #pragma unroll
                    for (int e = 0; e < 4; e++) acc[nj][e] = 0.f;
                #pragma unroll
                for (int ks = 0; ks < 2; ks++)
                    #pragma unroll
                    for (int nj = 0; nj < 2; nj++) {
                        mma16816(acc[nj], ah[ks], &bh[ks][nj*2]);
                        mma16816(acc[nj], ah[ks], &bl[ks][nj*2]);
                        mma16816(acc[nj], al[ks], &bh[ks][nj*2]);
                    }
                int row0 = mi*16 + (lane >> 2);
                int row1 = row0 + 8;
                #pragma unroll
                for (int nj = 0; nj < 2; nj++) {
                    int col = nbase + nj*8 + (lane & 3)*2;
                    #pragma unroll
                    for (int cc = 0; cc < 2; cc++) {
                        int m = col + cc;
                        int r0i = ((row0 >> 3) - (m >> 3) + 7)*15 + ((row0 & 7) - (m & 7) + 7);
                        int r1i = ((row1 >> 3) - (m >> 3) + 7)*15 + ((row1 & 7) - (m & 7) + 7);
                        Sx[row0*SPITCH + m] = acc[nj][cc]   * ls + sbias[r0i*4 + head];
                        Sx[row1*SPITCH + m] = acc[nj][cc+2] * ls + sbias[r1i*4 + head];
                    }
                }
            }
        }
        __syncthreads();

        {
            int r    = t >> 1;
            int half = t & 1;
            float* Sx   = (r < 64) ? S1 : S2;
            float* sums = (r < 64) ? ssum1 : ssum2;
            int rr = r & 63;
            float* row = Sx + rr*SPITCH + half*32;
            float mx = -1e30f;
            #pragma unroll
            for (int c = 0; c < 8; c++) {
                float4 v4 = *(const float4*)(row + c*4);
                mx = fmaxf(mx, fmaxf(fmaxf(v4.x, v4.y), fmaxf(v4.z, v4.w)));
            }
            mx = fmaxf(mx, __shfl_xor_sync(0xffffffffu, mx, 1));
            float sum = 0.f;
            #pragma unroll
            for (int c = 0; c < 8; c++) {
                float4 v4 = *(float4*)(row + c*4);
                v4.x = __expf(v4.x - mx); v4.y = __expf(v4.y - mx);
                v4.z = __expf(v4.z - mx); v4.w = __expf(v4.w - mx);
                sum += v4.x + v4.y + v4.z + v4.w;
                *(float4*)(row + c*4) = v4;
            }
            sum += __shfl_xor_sync(0xffffffffu, sum, 1);
            if (half == 0) sums[rr] = 1.f / sum;
        }
        __syncthreads();

        {
            float omg = 1.f - gt;
            #pragma unroll
            for (int u = 0; u < 16; u++) {
                int e = t*16 + u;
                int n = e >> 6, m = e & 63;
                float p = omg*S1[n*SPITCH + m]*ssum1[n] + gt*S2[n*SPITCH + m]*ssum2[n];
                __nv_bfloat16 ph = __float2bfloat16(p);
                PH[n*72 + m] = ph;
                PL[n*72 + m] = __float2bfloat16(p - __bfloat162float(ph));
            }
        }
        __syncthreads();

        {
            const int mi  = wid >> 1;
            const int njp = (wid & 1) * 2;
            uint32_t ah[4][4], al[4][4], bh[4][4], bl[4][4];
            #pragma unroll
            for (int ks = 0; ks < 4; ks++) {
                uint32_t offA = (uint32_t)((mi*16 + (lane & 15))*144 +
                                (ks*16 + ((lane >> 4) << 3))*2);
                ldsm4(ah[ks], su + sPH + offA);
                ldsm4(al[ks], su + sPL + offA);
                uint32_t offB = (uint32_t)((ks*16 + (lane & 15))*80 +
                                (njp*8 + ((lane >> 4) << 3))*2);
                ldsm4t(bh[ks], su + sVH + offB);
                ldsm4t(bl[ks], su + sVL + offB);
            }
            float acc[2][4];
            #pragma unroll
            for (int j = 0; j < 2; j++)
                #pragma unroll
                for (int e = 0; e < 4; e++) acc[j][e] = 0.f;
            #pragma unroll
            for (int ks = 0; ks < 4; ks++)
                #pragma unroll
                for (int j = 0; j < 2; j++) {
                    mma16816(acc[j], ah[ks], &bh[ks][j*2]);
                    mma16816(acc[j], ah[ks], &bl[ks][j*2]);
                    mma16816(acc[j], al[ks], &bh[ks][j*2]);
                }
            int row0 = mi*16 + (lane >> 2);
            int row1 = row0 + 8;
            size_t pix0 = (((size_t)b*IMGH + hw*8 + (row0 >> 3))*IMGW + (ww*8 + (row0 & 7)))*CDIM;
            size_t pix1 = (((size_t)b*IMGH + hw*8 + (row1 >> 3))*IMGW + (ww*8 + (row1 & 7)))*CDIM;
            #pragma unroll
            for (int j = 0; j < 2; j++) {
                int ch = head*32 + (njp + j)*8 + (lane & 3)*2;
                *(float2*)(g_imgA + pix0 + ch) = make_float2(acc[j][0], acc[j][1]);
                *(float2*)(g_imgA + pix1 + ch) = make_float2(acc[j][2], acc[j][3]);
            }
        }
        __syncthreads();
    }
}

// ---------------- bf16 tensor-core conv3x3: R7 shape + 3-stage B pipeline ----------------
__device__ __forceinline__ float* img_by_id(int id) {
    return id == 0 ? g_imgA : (id == 1 ? g_imgB : g_imgC);
}

// smem: A hi 100x272B @0, A lo @27200, B stages @54400 (3 x 8704: hi 16x272, lo +4352)
#define CONV_SMEM_BYTES 80512
#define A_PITCH_B 272
#define A_PITCH_E 136

__global__ __launch_bounds__(256) void conv3x3_mma(
    int in_id, int conv_idx, const float* __restrict__ bias,
    int res_id, int out_id, int relu)
{
    extern __shared__ __align__(16) unsigned char smem_raw[];
    __nv_bfloat16* aHiP = reinterpret_cast<__nv_bfloat16*>(smem_raw);
    __nv_bfloat16* aLoP = aHiP + 13600;
    const uint32_t smem_u = (uint32_t)__cvta_generic_to_shared(smem_raw);
    const uint32_t aHiU = smem_u;
    const uint32_t aLoU = smem_u + 27200;
    const uint32_t bU   = smem_u + 54400;

    const float* in  = img_by_id(in_id);
    float*       out = img_by_id(out_id);
    const float* res = (res_id >= 0) ? img_by_id(res_id) : nullptr;
    const __nv_bfloat16* wHi = g_wbf_hi + (size_t)conv_idx * KCONV * 128;
    const __nv_bfloat16* wLo = g_wbf_lo + (size_t)conv_idx * KCONV * 128;

    const int t    = threadIdx.x;
    const int lane = t & 31;
    const int wid  = t >> 5;
    const int warpM = wid >> 2;
    const int warpN = wid & 3;

    const int blk = blockIdx.x;
    const int b   = blk >> 10;
    const int th  = (blk & 1023) >> 5;
    const int tw  = blk & 31;
    const int h0  = th*8, w0 = tw*8;

    for (int idx = t; idx < 3200; idx += 256) {
        int r  = idx >> 5;
        int c4 = idx & 31;
        int hh = h0 + (r/10) - 1;
        int wp = w0 + (r%10) - 1;
        float4 v = make_float4(0.f, 0.f, 0.f, 0.f);
        if (hh >= 0 && hh < IMGH && wp >= 0 && wp < IMGW)
            v = *(const float4*)(in + (((size_t)b*IMGH + hh)*IMGW + wp)*CDIM + c4*4);
        split_store(aHiP, aLoP, r*A_PITCH_E + c4*4, v);
    }

    const int prow = t >> 4;
    const int pseg = t & 15;
    auto prefetchB = [&](int ks, int stage) {
        size_t gofs = ((size_t)(ks*16 + prow))*128 + pseg*8;
        uint32_t d = bU + stage*8704 + prow*A_PITCH_B + pseg*16;
        cp_async16(d,        wHi + gofs);
        cp_async16(d + 4352, wLo + gofs);
    };

    prefetchB(0, 0);
    asm volatile("cp.async.commit_group;");
    prefetchB(1, 1);
    asm volatile("cp.async.commit_group;");
    __syncthreads();

    float acc[2][4][4];
    #pragma unroll
    for (int mi = 0; mi < 2; mi++)
        #pragma unroll
        for (int ni = 0; ni < 4; ni++)
            #pragma unroll
            for (int e = 0; e < 4; e++) acc[mi][ni][e] = 0.f;

    int stage = 0;           // ks % 3
    int stage2 = 2;          // (ks+2) % 3
    for (int ks = 0; ks < 72; ks++) {
        if (ks < 70) {
            prefetchB(ks + 2, stage2);
            asm volatile("cp.async.commit_group;");
            asm volatile("cp.async.wait_group 2;");
        } else if (ks == 70) {
            asm volatile("cp.async.wait_group 1;");
        } else {
            asm volatile("cp.async.wait_group 0;");
        }
        __syncthreads();

        const int tap = ks >> 3;
        const int kc  = (ks & 7) << 4;
        const int dy  = tap / 3;
        const int dx  = tap - dy*3;

        uint32_t a_hi[2][4], a_lo[2][4];
        #pragma unroll
        for (int mi = 0; mi < 2; mi++) {
            int p = warpM*32 + mi*16 + (lane & 15);
            int r = ((p >> 3) + dy)*10 + (p & 7) + dx;
            uint32_t off = (uint32_t)(r*A_PITCH_B + (kc + ((lane >> 4) << 3))*2);
            ldsm4(a_hi[mi], aHiU + off);
            ldsm4(a_lo[mi], aLoU + off);
        }

        uint32_t b_hi[4][2], b_lo[4][2];
        const uint32_t bst = bU + stage*8704;
        #pragma unroll
        for (int pair = 0; pair < 2; pair++) {
            uint32_t off = (uint32_t)((lane & 15)*A_PITCH_B +
                           (warpN*32 + pair*16 + ((lane >> 4) << 3))*2);
            uint32_t r4[4];
            ldsm4t(r4, bst + off);
            b_hi[pair*2][0] = r4[0]; b_hi[pair*2][1] = r4[1];
            b_hi[pair*2+1][0] = r4[2]; b_hi[pair*2+1][1] = r4[3];
            ldsm4t(r4, bst + 4352 + off);
            b_lo[pair*2][0] = r4[0]; b_lo[pair*2][1] = r4[1];
            b_lo[pair*2+1][0] = r4[2]; b_lo[pair*2+1][1] = r4[3];
        }

        #pragma unroll
        for (int mi = 0; mi < 2; mi++)
            #pragma unroll
            for (int ni = 0; ni < 4; ni++) {
                mma16816(acc[mi][ni], a_hi[mi], b_hi[ni]);
                mma16816(acc[mi][ni], a_hi[mi], b_lo[ni]);
                mma16816(acc[mi][ni], a_lo[mi], b_hi[ni]);
            }
        __syncthreads();

        stage  = (stage  == 2) ? 0 : stage  + 1;
        stage2 = (stage2 == 2) ? 0 : stage2 + 1;
    }

    #pragma unroll
    for (int mi = 0; mi < 2; mi++) {
        #pragma unroll
        for (int ni = 0; ni < 4; ni++) {
            int p0 = warpM*32 + mi*16 + (lane >> 2);
            int p1 = p0 + 8;
            int ch = warpN*32 + ni*8 + (lane & 3)*2;
            float2 bb = *(const float2*)(bias + ch);
            float v00 = acc[mi][ni][0] + bb.x, v01 = acc[mi][ni][1] + bb.y;
            float v10 = acc[mi][ni][2] + bb.x, v11 = acc[mi][ni][3] + bb.y;
            if (relu) {
                v00 = fmaxf(v00, 0.f); v01 = fmaxf(v01, 0.f);
                v10 = fmaxf(v10, 0.f); v11 = fmaxf(v11, 0.f);
            }
            size_t g0 = (((size_t)b*IMGH + h0 + (p0 >> 3))*IMGW + w0 + (p0 & 7))*CDIM + ch;
            size_t g1 = (((size_t)b*IMGH + h0 + (p1 >> 3))*IMGW + w0 + (p1 & 7))*CDIM + ch;
            if (res) {
                float2 r0 = *(const float2*)(res + g0);
                float2 r1 = *(const float2*)(res + g1);
                v00 += r0.x; v01 += r0.y; v10 += r1.x; v11 += r1.y;
            }
            *(float2*)(out + g0) = make_float2(v00, v01);
            *(float2*)(out + g1) = make_float2(v10, v11);
        }
    }
}

// ================= proj 1x1 (mma) + window_partition -> d_out (unchanged) =================
#define PROJ_SMEM 52224
__global__ __launch_bounds__(256) void proj_mma(
    const float* __restrict__ proj_b, float* __restrict__ out)
{
    extern __shared__ __align__(16) unsigned char smem_raw[];
    __nv_bfloat16* aHiP = reinterpret_cast<__nv_bfloat16*>(smem_raw);
    __nv_bfloat16* aLoP = aHiP + 64*136;
    const uint32_t smem_u = (uint32_t)__cvta_generic_to_shared(smem_raw);
    const uint32_t aHiU = smem_u, aLoU = smem_u + 17408, bU = smem_u + 34816;

    const int t = threadIdx.x, lane = t & 31, wid = t >> 5;
    const int warpM = wid >> 2, warpN = wid & 3;
    const int win = blockIdx.x;
    const int b   = win >> 10;
    const int hw  = (win & 1023) >> 5;
    const int ww  = win & 31;
    const float* img = g_imgA;

    for (int idx = t; idx < 2048; idx += 256) {
        int tok = idx >> 5, c4 = idx & 31;
        int i1 = tok >> 3, j1 = tok & 7;
        size_t pix = (((size_t)b*IMGH + hw*8 + i1)*IMGW + (ww*8 + j1))*CDIM;
        float4 v = *(const float4*)(img + pix + c4*4);
        split_store(aHiP, aLoP, tok*136 + c4*4, v);
    }

    auto prefetchB = [&](int ks, int stage) {
        #pragma unroll
        for (int i = 0; i < 2; i++) {
            int c = t + i*256;
            int part = c >= 256; int cc = c - part*256;
            int row = cc >> 4, seg = cc & 15;
            const __nv_bfloat16* sp = (part ? g_wproj_lo : g_wproj_hi) + (ks*16 + row)*128 + seg*8;
            cp_async16(bU + stage*8704 + part*4352 + row*272 + seg*16, sp);
        }
    };
    prefetchB(0, 0);
    asm volatile("cp.async.commit_group;");
    __syncthreads();

    float acc[2][4][4];
    #pragma unroll
    for (int mi = 0; mi < 2; mi++)
        #pragma unroll
        for (int ni = 0; ni < 4; ni++)
            #pragma unroll
            for (int e = 0; e < 4; e++) acc[mi][ni][e] = 0.f;

    for (int ks = 0; ks < 8; ks++) {
        const int stage = ks & 1;
        if (ks < 7) {
            prefetchB(ks + 1, stage ^ 1);
            asm volatile("cp.async.commit_group;");
            asm volatile("cp.async.wait_group 1;");
        } else {
            asm volatile("cp.async.wait_group 0;");
        }
        __syncthreads();

        const int kc = ks * 16;
        uint32_t a_hi[2][4], a_lo[2][4];
        #pragma unroll
        for (int mi = 0; mi < 2; mi++) {
            int row = warpM*32 + mi*16 + (lane & 15);
            uint32_t off = (uint32_t)(row*272 + (kc + ((lane >> 4) << 3))*2);
            ldsm4(a_hi[mi], aHiU + off);
            ldsm4(a_lo[mi], aLoU + off);
        }
        const uint32_t bst = bU + stage*8704;
        #pragma unroll
        for (int pair = 0; pair < 2; pair++) {
            uint32_t off = (uint32_t)((lane & 15)*272 +
                           (warpN*32 + pair*16 + ((lane >> 4) << 3))*2);
            uint32_t bh[4], bl[4];
            ldsm4t(bh, bst + off);
            ldsm4t(bl, bst + 4352 + off);
            #pragma unroll
            for (int mi = 0; mi < 2; mi++) {
                mma16816(acc[mi][2*pair],   a_hi[mi], bh);
                mma16816(acc[mi][2*pair],   a_hi[mi], bl);
                mma16816(acc[mi][2*pair],   a_lo[mi], bh);
                mma16816(acc[mi][2*pair+1], a_hi[mi], bh+2);
                mma16816(acc[mi][2*pair+1], a_hi[mi], bl+2);
                mma16816(acc[mi][2*pair+1], a_lo[mi], bh+2);
            }
        }
        __syncthreads();
    }

    float* outw = out + (size_t)win * NTOK * CDIM;
    #pragma unroll
    for (int mi = 0; mi < 2; mi++) {
        int row0 = warpM*32 + mi*16 + (lane >> 2);
        int row1 = row0 + 8;
        #pragma unroll
        for (int ni = 0; ni < 4; ni++) {
            int ch = warpN*32 + ni*8 + (lane & 3)*2;
            float2 bb = *(const float2*)(proj_b + ch);
            *(float2*)(outw + row0*128 + ch) =
                make_float2(acc[mi][ni][0] + bb.x, acc[mi][ni][1] + bb.y);
            *(float2*)(outw + row1*128 + ch) =
                make_float2(acc[mi][ni][2] + bb.x, acc[mi][ni][3] + bb.y);
        }
    }
}

// ---------------- launch ----------------
extern "C" void kernel_launch(void* const* d_in, const int* in_sizes, int n_in,
                              void* d_out, int out_size) {
    const float* x         = (const float*)d_in[0];
    const float* ref       = (const float*)d_in[1];
    const float* qkv_w     = (const float*)d_in[2];
    const float* qkv_b     = (const float*)d_in[3];
    const float* proj_w    = (const float*)d_in[4];
    const float* proj_b    = (const float*)d_in[5];
    const float* t11w      = (const float*)d_in[6];
    const float* t11b      = (const float*)d_in[7];
    const float* t12w      = (const float*)d_in[8];
    const float* t12b      = (const float*)d_in[9];
    const float* t21w      = (const float*)d_in[10];
    const float* t21b      = (const float*)d_in[11];
    const float* t22w      = (const float*)d_in[12];
    const float* t22b      = (const float*)d_in[13];
    const float* rel_bias  = (const float*)d_in[14];
    const float* logit_sc  = (const float*)d_in[15];
    const float* gating    = (const float*)d_in[16];
    float* out = (float*)d_out;

    cudaFuncSetAttribute(attn_mma, cudaFuncAttributeMaxDynamicSharedMemorySize,
                         ATTN_SMEM_BYTES);
    cudaFuncSetAttribute(conv3x3_mma, cudaFuncAttributeMaxDynamicSharedMemorySize,
                         CONV_SMEM_BYTES);
    cudaFuncSetAttribute(qkv_mma,  cudaFuncAttributeMaxDynamicSharedMemorySize, QKV_SMEM);
    cudaFuncSetAttribute(kref_mma, cudaFuncAttributeMaxDynamicSharedMemorySize, KREF_SMEM);
    cudaFuncSetAttribute(proj_mma, cudaFuncAttributeMaxDynamicSharedMemorySize, PROJ_SMEM);

    prep_weights<<<192, 256>>>(qkv_w, proj_w);
    split_weights<<<(KCONV*128 + 255)/256, 256>>>(t11w, t12w, t21w, t22w);

    qkv_mma<<<NWIN, 256, QKV_SMEM>>>(x, qkv_b);
    kref_mma<<<NWIN, 256, KREF_SMEM>>>(ref, qkv_b);

    attn_mma<<<NWIN, 256, ATTN_SMEM_BYTES>>>(rel_bias, logit_sc, gating);

    conv3x3_mma<<<NWIN, 256, CONV_SMEM_BYTES>>>(0, 0, t11b, -1, 1, 1);
    conv3x3_mma<<<NWIN, 256, CONV_SMEM_BYTES>>>(1, 1, t12b,  0, 2, 0);
    conv3x3_mma<<<NWIN, 256, CONV_SMEM_BYTES>>>(2, 2, t21b, -1, 1, 1);
    conv3x3_mma<<<NWIN, 256, CONV_SMEM_BYTES>>>(1, 3, t22b,  2, 0, 0);

    proj_mma<<<NWIN, 256, PROJ_SMEM>>>(proj_b, out);
}

// round 12
// speedup vs baseline: 1.0958x; 1.0958x over previous
#include <cuda_runtime.h>
#include <cuda_bf16.h>
#include <cstdint>
#include <cstddef>

// ---------------- constants ----------------
#define NWIN   2048
#define NTOK   64
#define CDIM   128
#define NHEAD  4
#define HDIM   32
#define IMGH   256
#define IMGW   256
#define NB     2
#define KCONV  1152          // 9*128

// ---------------- scratch ----------------
// q, v: [win][head][tok][32] bf16 hi/lo.  k, kref: TRANSPOSED [win][head][ch][64].
__device__ __align__(16) __nv_bfloat16 g_qh [NWIN*NHEAD*NTOK*HDIM];
__device__ __align__(16) __nv_bfloat16 g_ql [NWIN*NHEAD*NTOK*HDIM];
__device__ __align__(16) __nv_bfloat16 g_kh [NWIN*NHEAD*NTOK*HDIM];
__device__ __align__(16) __nv_bfloat16 g_kl [NWIN*NHEAD*NTOK*HDIM];
__device__ __align__(16) __nv_bfloat16 g_krh[NWIN*NHEAD*NTOK*HDIM];
__device__ __align__(16) __nv_bfloat16 g_krl[NWIN*NHEAD*NTOK*HDIM];
__device__ __align__(16) __nv_bfloat16 g_vh [NWIN*NHEAD*NTOK*HDIM];
__device__ __align__(16) __nv_bfloat16 g_vl [NWIN*NHEAD*NTOK*HDIM];
__device__ float g_imgA[(size_t)NB*IMGH*IMGW*CDIM];
__device__ float g_imgB[(size_t)NB*IMGH*IMGW*CDIM];
__device__ float g_imgC[(size_t)NB*IMGH*IMGW*CDIM];
__device__ __nv_bfloat16 g_wbf_hi[4*KCONV*128];   // conv weights [conv][k][o]
__device__ __nv_bfloat16 g_wbf_lo[4*KCONV*128];
__device__ __nv_bfloat16 g_wqkv_hi[128*384];      // [k][o]
__device__ __nv_bfloat16 g_wqkv_lo[128*384];
__device__ __nv_bfloat16 g_wproj_hi[128*128];     // [k][o]
__device__ __nv_bfloat16 g_wproj_lo[128*128];

// ---------------- weight prep: transpose + hi/lo split ----------------
__global__ void prep_weights(const float* __restrict__ qkv_w,
                             const float* __restrict__ proj_w) {
    int t = blockIdx.x * blockDim.x + threadIdx.x;   // 0..49151
    if (t < 384*128) {
        int o = t / 128, k = t % 128;
        float x = qkv_w[t];
        __nv_bfloat16 hi = __float2bfloat16(x);
        g_wqkv_hi[k*384 + o] = hi;
        g_wqkv_lo[k*384 + o] = __float2bfloat16(x - __bfloat162float(hi));
    }
    if (t < 128*128) {
        int o = t / 128, k = t % 128;
        float x = proj_w[t];
        __nv_bfloat16 hi = __float2bfloat16(x);
        g_wproj_hi[k*128 + o] = hi;
        g_wproj_lo[k*128 + o] = __float2bfloat16(x - __bfloat162float(hi));
    }
}

__global__ void split_weights(const float* __restrict__ w0, const float* __restrict__ w1,
                              const float* __restrict__ w2, const float* __restrict__ w3) {
    int t = blockIdx.x * blockDim.x + threadIdx.x;
    if (t >= KCONV*128) return;
    const float* ws[4] = {w0, w1, w2, w3};
    #pragma unroll
    for (int c = 0; c < 4; c++) {
        float x = ws[c][t];
        __nv_bfloat16 hi = __float2bfloat16(x);
        float lo = x - __bfloat162float(hi);
        g_wbf_hi[c*KCONV*128 + t] = hi;
        g_wbf_lo[c*KCONV*128 + t] = __float2bfloat16(lo);
    }
}

// ---------------- mma helpers ----------------
__device__ __forceinline__ void ldsm4(uint32_t* r, uint32_t addr) {
    asm volatile("ldmatrix.sync.aligned.m8n8.x4.shared.b16 {%0,%1,%2,%3}, [%4];"
        : "=r"(r[0]), "=r"(r[1]), "=r"(r[2]), "=r"(r[3]) : "r"(addr));
}
__device__ __forceinline__ void ldsm4t(uint32_t* r, uint32_t addr) {
    asm volatile("ldmatrix.sync.aligned.m8n8.x4.trans.shared.b16 {%0,%1,%2,%3}, [%4];"
        : "=r"(r[0]), "=r"(r[1]), "=r"(r[2]), "=r"(r[3]) : "r"(addr));
}
__device__ __forceinline__ void mma16816(float* c, const uint32_t* a, const uint32_t* b) {
    asm volatile("mma.sync.aligned.m16n8k16.row.col.f32.bf16.bf16.f32 "
        "{%0,%1,%2,%3}, {%4,%5,%6,%7}, {%8,%9}, {%0,%1,%2,%3};"
        : "+f"(c[0]), "+f"(c[1]), "+f"(c[2]), "+f"(c[3])
        : "r"(a[0]), "r"(a[1]), "r"(a[2]), "r"(a[3]), "r"(b[0]), "r"(b[1]));
}
__device__ __forceinline__ void cp_async16(uint32_t dst, const void* src) {
    asm volatile("cp.async.cg.shared.global [%0], [%1], 16;" :: "r"(dst), "l"(src));
}
__device__ __forceinline__ void split_store(__nv_bfloat16* hiP, __nv_bfloat16* loP,
                                            int off, float4 v) {
    __nv_bfloat16 hx = __float2bfloat16(v.x), hy = __float2bfloat16(v.y);
    __nv_bfloat16 hz = __float2bfloat16(v.z), hw = __float2bfloat16(v.w);
    uint32_t h01 = ((uint32_t)__bfloat16_as_ushort(hy) << 16) | __bfloat16_as_ushort(hx);
    uint32_t h23 = ((uint32_t)__bfloat16_as_ushort(hw) << 16) | __bfloat16_as_ushort(hz);
    __nv_bfloat16 l0 = __float2bfloat16(v.x - __bfloat162float(hx));
    __nv_bfloat16 l1 = __float2bfloat16(v.y - __bfloat162float(hy));
    __nv_bfloat16 l2 = __float2bfloat16(v.z - __bfloat162float(hz));
    __nv_bfloat16 l3 = __float2bfloat16(v.w - __bfloat162float(hw));
    uint32_t lo01 = ((uint32_t)__bfloat16_as_ushort(l1) << 16) | __bfloat16_as_ushort(l0);
    uint32_t lo23 = ((uint32_t)__bfloat16_as_ushort(l3) << 16) | __bfloat16_as_ushort(l2);
    *(uint32_t*)(hiP + off)     = h01;
    *(uint32_t*)(hiP + off + 2) = h23;
    *(uint32_t*)(loP + off)     = lo01;
    *(uint32_t*)(loP + off + 2) = lo23;
}
__device__ __forceinline__ void st_pair(__nv_bfloat16* hp, __nv_bfloat16* lp,
                                        float x0, float x1) {
    __nv_bfloat16 h0 = __float2bfloat16(x0), h1 = __float2bfloat16(x1);
    *(__nv_bfloat162*)hp = __halves2bfloat162(h0, h1);
    *(__nv_bfloat162*)lp = __halves2bfloat162(
        __float2bfloat16(x0 - __bfloat162float(h0)),
        __float2bfloat16(x1 - __bfloat162float(h1)));
}

// ================= fused QKV (x branch): GEMM 64x384x128 + per-head norm =================
#define QKV_SMEM 84992
__global__ __launch_bounds__(256) void qkv_mma(
    const float* __restrict__ src, const float* __restrict__ qkv_b)
{
    extern __shared__ __align__(16) unsigned char smem_raw[];
    __nv_bfloat16* aHiP = reinterpret_cast<__nv_bfloat16*>(smem_raw);
    __nv_bfloat16* aLoP = aHiP + 64*136;
    const uint32_t smem_u = (uint32_t)__cvta_generic_to_shared(smem_raw);
    const uint32_t aHiU = smem_u, aLoU = smem_u + 17408, bU = smem_u + 34816;

    const int t = threadIdx.x, lane = t & 31, wid = t >> 5;
    const int warpM = wid >> 2, warpN = wid & 3;   // 2 x 4, warp tile 32 x 96
    const int win = blockIdx.x;
    const float* srcw = src + (size_t)win * NTOK * CDIM;

    for (int idx = t; idx < 2048; idx += 256) {
        int r = idx >> 5, c4 = idx & 31;
        float4 v = *(const float4*)(srcw + r*128 + c4*4);
        split_store(aHiP, aLoP, r*136 + c4*4, v);
    }

    auto prefetchB = [&](int ks, int stage) {
        #pragma unroll
        for (int i = 0; i < 6; i++) {
            int c = t + i*256;
            int part = c >= 768; int cc = c - part*768;
            int row = cc / 48, seg = cc % 48;
            const __nv_bfloat16* sp = (part ? g_wqkv_lo : g_wqkv_hi) + (ks*16 + row)*384 + seg*8;
            cp_async16(bU + stage*25088 + part*12544 + row*784 + seg*16, sp);
        }
    };
    prefetchB(0, 0);
    asm volatile("cp.async.commit_group;");
    __syncthreads();

    float acc[2][12][4];
    #pragma unroll
    for (int mi = 0; mi < 2; mi++)
        #pragma unroll
        for (int ni = 0; ni < 12; ni++)
            #pragma unroll
            for (int e = 0; e < 4; e++) acc[mi][ni][e] = 0.f;

    for (int ks = 0; ks < 8; ks++) {
        const int stage = ks & 1;
        if (ks < 7) {
            prefetchB(ks + 1, stage ^ 1);
            asm volatile("cp.async.commit_group;");
            asm volatile("cp.async.wait_group 1;");
        } else {
            asm volatile("cp.async.wait_group 0;");
        }
        __syncthreads();

        const int kc = ks * 16;
        uint32_t a_hi[2][4], a_lo[2][4];
        #pragma unroll
        for (int mi = 0; mi < 2; mi++) {
            int row = warpM*32 + mi*16 + (lane & 15);
            uint32_t off = (uint32_t)(row*272 + (kc + ((lane >> 4) << 3))*2);
            ldsm4(a_hi[mi], aHiU + off);
            ldsm4(a_lo[mi], aLoU + off);
        }
        const uint32_t bst = bU + stage*25088;
        #pragma unroll
        for (int pair = 0; pair < 6; pair++) {
            uint32_t off = (uint32_t)((lane & 15)*784 +
                           (warpN*96 + pair*16 + ((lane >> 4) << 3))*2);
            uint32_t bh[4], bl[4];
            ldsm4t(bh, bst + off);
            ldsm4t(bl, bst + 12544 + off);
            #pragma unroll
            for (int mi = 0; mi < 2; mi++) {
                mma16816(acc[mi][2*pair],   a_hi[mi], bh);
                mma16816(acc[mi][2*pair],   a_hi[mi], bl);
                mma16816(acc[mi][2*pair],   a_lo[mi], bh);
                mma16816(acc[mi][2*pair+1], a_hi[mi], bh+2);
                mma16816(acc[mi][2*pair+1], a_hi[mi], bl+2);
                mma16816(acc[mi][2*pair+1], a_lo[mi], bh+2);
            }
        }
        __syncthreads();
    }

    // epilogue: bias, per-head L2 norm (q,k), store bf16 hi/lo (k transposed)
    #pragma unroll
    for (int mi = 0; mi < 2; mi++) {
        int row0 = warpM*32 + mi*16 + (lane >> 2);
        int row1 = row0 + 8;
        #pragma unroll
        for (int ni = 0; ni < 12; ni++) {
            int col = warpN*96 + ni*8 + (lane & 3)*2;
            float2 bb = *(const float2*)(qkv_b + col);
            acc[mi][ni][0] += bb.x; acc[mi][ni][1] += bb.y;
            acc[mi][ni][2] += bb.x; acc[mi][ni][3] += bb.y;
        }
        #pragma unroll
        for (int sg = 0; sg < 3; sg++) {
            float s0 = 0.f, s1 = 0.f;
            #pragma unroll
            for (int k = 0; k < 4; k++) {
                int ni = sg*4 + k;
                s0 += acc[mi][ni][0]*acc[mi][ni][0] + acc[mi][ni][1]*acc[mi][ni][1];
                s1 += acc[mi][ni][2]*acc[mi][ni][2] + acc[mi][ni][3]*acc[mi][ni][3];
            }
            s0 += __shfl_xor_sync(0xffffffffu, s0, 1);
            s0 += __shfl_xor_sync(0xffffffffu, s0, 2);
            s1 += __shfl_xor_sync(0xffffffffu, s1, 1);
            s1 += __shfl_xor_sync(0xffffffffu, s1, 2);
            int gcol = warpN*96 + sg*32;
            int sec = gcol >> 7, head = (gcol >> 5) & 3;
            float sc0 = 1.f, sc1 = 1.f;
            if (sec < 2) {
                sc0 = 1.f / fmaxf(sqrtf(s0), 1e-12f);
                sc1 = 1.f / fmaxf(sqrtf(s1), 1e-12f);
            }
            const size_t base = (size_t)(win*4 + head) * 2048;
            #pragma unroll
            for (int k = 0; k < 4; k++) {
                int ni = sg*4 + k;
                int d = k*8 + (lane & 3)*2;
                float x0 = acc[mi][ni][0]*sc0, x1 = acc[mi][ni][1]*sc0;
                float x2 = acc[mi][ni][2]*sc1, x3 = acc[mi][ni][3]*sc1;
                if (sec == 0) {
                    st_pair(g_qh + base + row0*32 + d, g_ql + base + row0*32 + d, x0, x1);
                    st_pair(g_qh + base + row1*32 + d, g_ql + base + row1*32 + d, x2, x3);
                } else if (sec == 2) {
                    st_pair(g_vh + base + row0*32 + d, g_vl + base + row0*32 + d, x0, x1);
                    st_pair(g_vh + base + row1*32 + d, g_vl + base + row1*32 + d, x2, x3);
                } else {
                    __nv_bfloat16 h;
                    h = __float2bfloat16(x0); g_kh[base + d*64 + row0] = h;
                    g_kl[base + d*64 + row0] = __float2bfloat16(x0 - __bfloat162float(h));
                    h = __float2bfloat16(x1); g_kh[base + (d+1)*64 + row0] = h;
                    g_kl[base + (d+1)*64 + row0] = __float2bfloat16(x1 - __bfloat162float(h));
                    h = __float2bfloat16(x2); g_kh[base + d*64 + row1] = h;
                    g_kl[base + d*64 + row1] = __float2bfloat16(x2 - __bfloat162float(h));
                    h = __float2bfloat16(x3); g_kh[base + (d+1)*64 + row1] = h;
                    g_kl[base + (d+1)*64 + row1] = __float2bfloat16(x3 - __bfloat162float(h));
                }
            }
        }
    }
}

// ================= k_ref: GEMM 64x128x128 (weight cols 128..255) + norm, transposed out =================
#define KREF_SMEM 52224
__global__ __launch_bounds__(256) void kref_mma(
    const float* __restrict__ src, const float* __restrict__ qkv_b)
{
    extern __shared__ __align__(16) unsigned char smem_raw[];
    __nv_bfloat16* aHiP = reinterpret_cast<__nv_bfloat16*>(smem_raw);
    __nv_bfloat16* aLoP = aHiP + 64*136;
    const uint32_t smem_u = (uint32_t)__cvta_generic_to_shared(smem_raw);
    const uint32_t aHiU = smem_u, aLoU = smem_u + 17408, bU = smem_u + 34816;

    const int t = threadIdx.x, lane = t & 31, wid = t >> 5;
    const int warpM = wid >> 2, warpN = wid & 3;
    const int win = blockIdx.x;
    const float* srcw = src + (size_t)win * NTOK * CDIM;

    for (int idx = t; idx < 2048; idx += 256) {
        int r = idx >> 5, c4 = idx & 31;
        float4 v = *(const float4*)(srcw + r*128 + c4*4);
        split_store(aHiP, aLoP, r*136 + c4*4, v);
    }

    auto prefetchB = [&](int ks, int stage) {
        #pragma unroll
        for (int i = 0; i < 2; i++) {
            int c = t + i*256;
            int part = c >= 256; int cc = c - part*256;
            int row = cc >> 4, seg = cc & 15;
            const __nv_bfloat16* sp = (part ? g_wqkv_lo : g_wqkv_hi) + (ks*16 + row)*384 + 128 + seg*8;
            cp_async16(bU + stage*8704 + part*4352 + row*272 + seg*16, sp);
        }
    };
    prefetchB(0, 0);
    asm volatile("cp.async.commit_group;");
    __syncthreads();

    float acc[2][4][4];
    #pragma unroll
    for (int mi = 0; mi < 2; mi++)
        #pragma unroll
        for (int ni = 0; ni < 4; ni++)
            #pragma unroll
            for (int e = 0; e < 4; e++) acc[mi][ni][e] = 0.f;

    for (int ks = 0; ks < 8; ks++) {
        const int stage = ks & 1;
        if (ks < 7) {
            prefetchB(ks + 1, stage ^ 1);
            asm volatile("cp.async.commit_group;");
            asm volatile("cp.async.wait_group 1;");
        } else {
            asm volatile("cp.async.wait_group 0;");
        }
        __syncthreads();

        const int kc = ks * 16;
        uint32_t a_hi[2][4], a_lo[2][4];
        #pragma unroll
        for (int mi = 0; mi < 2; mi++) {
            int row = warpM*32 + mi*16 + (lane & 15);
            uint32_t off = (uint32_t)(row*272 + (kc + ((lane >> 4) << 3))*2);
            ldsm4(a_hi[mi], aHiU + off);
            ldsm4(a_lo[mi], aLoU + off);
        }
        const uint32_t bst = bU + stage*8704;
        #pragma unroll
        for (int pair = 0; pair < 2; pair++) {
            uint32_t off = (uint32_t)((lane & 15)*272 +
                           (warpN*32 + pair*16 + ((lane >> 4) << 3))*2);
            uint32_t bh[4], bl[4];
            ldsm4t(bh, bst + off);
            ldsm4t(bl, bst + 4352 + off);
            #pragma unroll
            for (int mi = 0; mi < 2; mi++) {
                mma16816(acc[mi][2*pair],   a_hi[mi], bh);
                mma16816(acc[mi][2*pair],   a_hi[mi], bl);
                mma16816(acc[mi][2*pair],   a_lo[mi], bh);
                mma16816(acc[mi][2*pair+1], a_hi[mi], bh+2);
                mma16816(acc[mi][2*pair+1], a_hi[mi], bl+2);
                mma16816(acc[mi][2*pair+1], a_lo[mi], bh+2);
            }
        }
        __syncthreads();
    }

    #pragma unroll
    for (int mi = 0; mi < 2; mi++) {
        int row0 = warpM*32 + mi*16 + (lane >> 2);
        int row1 = row0 + 8;
        #pragma unroll
        for (int ni = 0; ni < 4; ni++) {
            int col = warpN*32 + ni*8 + (lane & 3)*2;
            float2 bb = *(const float2*)(qkv_b + 128 + col);
            acc[mi][ni][0] += bb.x; acc[mi][ni][1] += bb.y;
            acc[mi][ni][2] += bb.x; acc[mi][ni][3] += bb.y;
        }
        float s0 = 0.f, s1 = 0.f;
        #pragma unroll
        for (int ni = 0; ni < 4; ni++) {
            s0 += acc[mi][ni][0]*acc[mi][ni][0] + acc[mi][ni][1]*acc[mi][ni][1];
            s1 += acc[mi][ni][2]*acc[mi][ni][2] + acc[mi][ni][3]*acc[mi][ni][3];
        }
        s0 += __shfl_xor_sync(0xffffffffu, s0, 1);
        s0 += __shfl_xor_sync(0xffffffffu, s0, 2);
        s1 += __shfl_xor_sync(0xffffffffu, s1, 1);
        s1 += __shfl_xor_sync(0xffffffffu, s1, 2);
        float sc0 = 1.f / fmaxf(sqrtf(s0), 1e-12f);
        float sc1 = 1.f / fmaxf(sqrtf(s1), 1e-12f);
        const size_t base = (size_t)(win*4 + warpN) * 2048;   // head = warpN
        #pragma unroll
        for (int ni = 0; ni < 4; ni++) {
            int d = ni*8 + (lane & 3)*2;
            float x0 = acc[mi][ni][0]*sc0, x1 = acc[mi][ni][1]*sc0;
            float x2 = acc[mi][ni][2]*sc1, x3 = acc[mi][ni][3]*sc1;
            __nv_bfloat16 h;
            h = __float2bfloat16(x0); g_krh[base + d*64 + row0] = h;
            g_krl[base + d*64 + row0] = __float2bfloat16(x0 - __bfloat162float(h));
            h = __float2bfloat16(x1); g_krh[base + (d+1)*64 + row0] = h;
            g_krl[base + (d+1)*64 + row0] = __float2bfloat16(x1 - __bfloat162float(h));
            h = __float2bfloat16(x2); g_krh[base + d*64 + row1] = h;
            g_krl[base + d*64 + row1] = __float2bfloat16(x2 - __bfloat162float(h));
            h = __float2bfloat16(x3); g_krh[base + (d+1)*64 + row1] = h;
            g_krl[base + (d+1)*64 + row1] = __float2bfloat16(x3 - __bfloat162float(h));
        }
    }
}

// ---------------- attention: tensor-core scores + AV, inter-head cp.async pipeline ----------------
#define sQH 0
#define sQL 5120
#define sKH 10240
#define sKL 14848
#define sRH 19456
#define sRL 24064
#define sVH 28672
#define sVL 33792
#define sPH 38912
#define sPL 48128
#define sS1 57344
#define sS2 74752
#define sBIAS 92160
#define sSUM 95760
#define ATTN_SMEM_BYTES 96512
#define SPITCH 68

__global__ __launch_bounds__(256) void attn_mma(
    const float* __restrict__ rel_bias, const float* __restrict__ logit_scale,
    const float* __restrict__ gating)
{
    extern __shared__ __align__(16) unsigned char smem_raw[];
    const uint32_t su = (uint32_t)__cvta_generic_to_shared(smem_raw);
    float* S1    = (float*)(smem_raw + sS1);
    float* S2    = (float*)(smem_raw + sS2);
    float* sbias = (float*)(smem_raw + sBIAS);
    float* ssum1 = (float*)(smem_raw + sSUM);
    float* ssum2 = ssum1 + 64;
    __nv_bfloat16* PH = (__nv_bfloat16*)(smem_raw + sPH);
    __nv_bfloat16* PL = (__nv_bfloat16*)(smem_raw + sPL);

    const int t = threadIdx.x, lane = t & 31, wid = t >> 5;
    const int win = blockIdx.x;
    const int b   = win >> 10;
    const int hw  = (win & 1023) >> 5;
    const int ww  = win & 31;

    // per-thread load offsets
    const int rq = t >> 2, cq = t & 3;     // q/v: 64 rows x 4 chunks
    const int rk = t >> 3, ck = t & 7;     // k/kr: 32 rows x 8 chunks

    auto issue_qkr = [&](int head) {
        const size_t base = (size_t)(win*4 + head) * 2048;
        cp_async16(su + sQH + rq*80 + cq*16, g_qh + base + rq*32 + cq*8);
        cp_async16(su + sQL + rq*80 + cq*16, g_ql + base + rq*32 + cq*8);
        cp_async16(su + sKH + rk*144 + ck*16, g_kh  + base + rk*64 + ck*8);
        cp_async16(su + sKL + rk*144 + ck*16, g_kl  + base + rk*64 + ck*8);
        cp_async16(su + sRH + rk*144 + ck*16, g_krh + base + rk*64 + ck*8);
        cp_async16(su + sRL + rk*144 + ck*16, g_krl + base + rk*64 + ck*8);
        asm volatile("cp.async.commit_group;");
    };
    auto issue_v = [&](int head) {
        const size_t base = (size_t)(win*4 + head) * 2048;
        cp_async16(su + sVH + rq*80 + cq*16, g_vh + base + rq*32 + cq*8);
        cp_async16(su + sVL + rq*80 + cq*16, g_vl + base + rq*32 + cq*8);
        asm volatile("cp.async.commit_group;");
    };

    // prologue: head 0 loads in flight while bias table loads
    issue_qkr(0);
    issue_v(0);
    for (int i = t; i < 900; i += 256) sbias[i] = rel_bias[i];

    for (int head = 0; head < 4; head++) {
        float ls = __expf(fminf(logit_scale[head], 4.6051702f));
        float gt = 1.f / (1.f + __expf(-gating[head]));

        asm volatile("cp.async.wait_group 0;");
        __syncthreads();

        // ---- scores: warps 0-3 -> S1 (K), warps 4-7 -> S2 (Kref); each warp 64x16 ----
        {
            const int mat = wid >> 2;
            const int nbase = (wid & 3) * 16;
            const uint32_t bHu = su + (mat ? sRH : sKH);
            const uint32_t bLu = su + (mat ? sRL : sKL);
            float* Sx = mat ? S2 : S1;

            uint32_t bh[2][4], bl[2][4];
            #pragma unroll
            for (int ks = 0; ks < 2; ks++) {
                uint32_t off = (uint32_t)((ks*16 + (lane & 15))*144 +
                               (nbase + ((lane >> 4) << 3))*2);
                ldsm4t(bh[ks], bHu + off);
                ldsm4t(bl[ks], bLu + off);
            }
            #pragma unroll
            for (int mi = 0; mi < 4; mi++) {
                uint32_t ah[2][4], al[2][4];
                #pragma unroll
                for (int ks = 0; ks < 2; ks++) {
                    uint32_t off = (uint32_t)((mi*16 + (lane & 15))*80 +
                                   (ks*16 + ((lane >> 4) << 3))*2);
                    ldsm4(ah[ks], su + sQH + off);
                    ldsm4(al[ks], su + sQL + off);
                }
                float acc[2][4];
                #pragma unroll
                for (int nj = 0; nj < 2; nj++)
                    #pragma unroll
                    for (int e = 0; e < 4; e++) acc[nj][e] = 0.f;
                #pragma unroll
                for (int ks = 0; ks < 2; ks++)
                    #pragma unroll
                    for (int nj = 0; nj < 2; nj++) {
                        mma16816(acc[nj], ah[ks], &bh[ks][nj*2]);
                        mma16816(acc[nj], ah[ks], &bl[ks][nj*2]);
                        mma16816(acc[nj], al[ks], &bh[ks][nj*2]);
                    }
                int row0 = mi*16 + (lane >> 2);
                int row1 = row0 + 8;
                #pragma unroll
                for (int nj = 0; nj < 2; nj++) {
                    int col = nbase + nj*8 + (lane & 3)*2;
                    #pragma unroll
                    for (int cc = 0; cc < 2; cc++) {
                        int m = col + cc;
                        int r0i = ((row0 >> 3) - (m >> 3) + 7)*15 + ((row0 & 7) - (m & 7) + 7);
                        int r1i = ((row1 >> 3) - (m >> 3) + 7)*15 + ((row1 & 7) - (m & 7) + 7);
                        Sx[row0*SPITCH + m] = acc[nj][cc]   * ls + sbias[r0i*4 + head];
                        Sx[row1*SPITCH + m] = acc[nj][cc+2] * ls + sbias[r1i*4 + head];
                    }
                }
            }
        }
        __syncthreads();

        // Q/K/R buffers now dead -> prefetch next head's Q/K/R under softmax+gate+AV
        if (head < 3) issue_qkr(head + 1);

        // ---- parallel softmax: 2 threads per row, 128 rows ----
        {
            int r    = t >> 1;
            int half = t & 1;
            float* Sx   = (r < 64) ? S1 : S2;
            float* sums = (r < 64) ? ssum1 : ssum2;
            int rr = r & 63;
            float* row = Sx + rr*SPITCH + half*32;
            float mx = -1e30f;
            #pragma unroll
            for (int c = 0; c < 8; c++) {
                float4 v4 = *(const float4*)(row + c*4);
                mx = fmaxf(mx, fmaxf(fmaxf(v4.x, v4.y), fmaxf(v4.z, v4.w)));
            }
            mx = fmaxf(mx, __shfl_xor_sync(0xffffffffu, mx, 1));
            float sum = 0.f;
            #pragma unroll
            for (int c = 0; c < 8; c++) {
                float4 v4 = *(float4*)(row + c*4);
                v4.x = __expf(v4.x - mx); v4.y = __expf(v4.y - mx);
                v4.z = __expf(v4.z - mx); v4.w = __expf(v4.w - mx);
                sum += v4.x + v4.y + v4.z + v4.w;
                *(float4*)(row + c*4) = v4;
            }
            sum += __shfl_xor_sync(0xffffffffu, sum, 1);
            if (half == 0) sums[rr] = 1.f / sum;
        }
        __syncthreads();

        // ---- normalize + gate -> P bf16 hi/lo [n][m] pitch 72 ----
        {
            float omg = 1.f - gt;
            #pragma unroll
            for (int u = 0; u < 16; u++) {
                int e = t*16 + u;
                int n = e >> 6, m = e & 63;
                float p = omg*S1[n*SPITCH + m]*ssum1[n] + gt*S2[n*SPITCH + m]*ssum2[n];
                __nv_bfloat16 ph = __float2bfloat16(p);
                PH[n*72 + m] = ph;
                PL[n*72 + m] = __float2bfloat16(p - __bfloat162float(ph));
            }
        }
        __syncthreads();

        // ---- AV: out[tok][32] = P(64x64) x V(64x32) ----
        {
            const int mi  = wid >> 1;
            const int njp = (wid & 1) * 2;
            uint32_t ah[4][4], al[4][4], bh[4][4], bl[4][4];
            #pragma unroll
            for (int ks = 0; ks < 4; ks++) {
                uint32_t offA = (uint32_t)((mi*16 + (lane & 15))*144 +
                                (ks*16 + ((lane >> 4) << 3))*2);
                ldsm4(ah[ks], su + sPH + offA);
                ldsm4(al[ks], su + sPL + offA);
                uint32_t offB = (uint32_t)((ks*16 + (lane & 15))*80 +
                                (njp*8 + ((lane >> 4) << 3))*2);
                ldsm4t(bh[ks], su + sVH + offB);
                ldsm4t(bl[ks], su + sVL + offB);
            }
            float acc[2][4];
            #pragma unroll
            for (int j = 0; j < 2; j++)
                #pragma unroll
                for (int e = 0; e < 4; e++) acc[j][e] = 0.f;
            #pragma unroll
            for (int ks = 0; ks < 4; ks++)
                #pragma unroll
                for (int j = 0; j < 2; j++) {
                    mma16816(acc[j], ah[ks], &bh[ks][j*2]);
                    mma16816(acc[j], ah[ks], &bl[ks][j*2]);
                    mma16816(acc[j], al[ks], &bh[ks][j*2]);
                }
            int row0 = mi*16 + (lane >> 2);
            int row1 = row0 + 8;
            size_t pix0 = (((size_t)b*IMGH + hw*8 + (row0 >> 3))*IMGW + (ww*8 + (row0 & 7)))*CDIM;
            size_t pix1 = (((size_t)b*IMGH + hw*8 + (row1 >> 3))*IMGW + (ww*8 + (row1 & 7)))*CDIM;
            #pragma unroll
            for (int j = 0; j < 2; j++) {
                int ch = head*32 + (njp + j)*8 + (lane & 3)*2;
                *(float2*)(g_imgA + pix0 + ch) = make_float2(acc[j][0], acc[j][1]);
                *(float2*)(g_imgA + pix1 + ch) = make_float2(acc[j][2], acc[j][3]);
            }
        }
        __syncthreads();

        // V buffer now dead -> prefetch next head's V
        if (head < 3) issue_v(head + 1);
    }
}

// ---------------- bf16 tensor-core conv3x3 (exact R7 champion config) ----------------
__device__ __forceinline__ float* img_by_id(int id) {
    return id == 0 ? g_imgA : (id == 1 ? g_imgB : g_imgC);
}

#define CONV_SMEM_BYTES 71808
#define A_PITCH_B 272
#define A_PITCH_E 136

__global__ __launch_bounds__(256) void conv3x3_mma(
    int in_id, int conv_idx, const float* __restrict__ bias,
    int res_id, int out_id, int relu)
{
    extern __shared__ __align__(16) unsigned char smem_raw[];
    __nv_bfloat16* aHiP = reinterpret_cast<__nv_bfloat16*>(smem_raw);
    __nv_bfloat16* aLoP = aHiP + 13600;
    const uint32_t smem_u = (uint32_t)__cvta_generic_to_shared(smem_raw);
    const uint32_t aHiU = smem_u;
    const uint32_t aLoU = smem_u + 27200;
    const uint32_t bU   = smem_u + 54400;

    const float* in  = img_by_id(in_id);
    float*       out = img_by_id(out_id);
    const float* res = (res_id >= 0) ? img_by_id(res_id) : nullptr;
    const __nv_bfloat16* wHi = g_wbf_hi + (size_t)conv_idx * KCONV * 128;
    const __nv_bfloat16* wLo = g_wbf_lo + (size_t)conv_idx * KCONV * 128;

    const int t    = threadIdx.x;
    const int lane = t & 31;
    const int wid  = t >> 5;
    const int warpM = wid >> 2;
    const int warpN = wid & 3;

    const int blk = blockIdx.x;
    const int b   = blk >> 10;
    const int th  = (blk & 1023) >> 5;
    const int tw  = blk & 31;
    const int h0  = th*8, w0 = tw*8;

    for (int idx = t; idx < 3200; idx += 256) {
        int r  = idx >> 5;
        int c4 = idx & 31;
        int hh = h0 + (r/10) - 1;
        int wp = w0 + (r%10) - 1;
        float4 v = make_float4(0.f, 0.f, 0.f, 0.f);
        if (hh >= 0 && hh < IMGH && wp >= 0 && wp < IMGW)
            v = *(const float4*)(in + (((size_t)b*IMGH + hh)*IMGW + wp)*CDIM + c4*4);
        split_store(aHiP, aLoP, r*A_PITCH_E + c4*4, v);
    }

    const int prow = t >> 4;
    const int pseg = t & 15;
    auto prefetchB = [&](int ks, int stage) {
        size_t gofs = ((size_t)(ks*16 + prow))*128 + pseg*8;
        uint32_t d = bU + stage*8704 + prow*A_PITCH_B + pseg*16;
        cp_async16(d,        wHi + gofs);
        cp_async16(d + 4352, wLo + gofs);
    };

    prefetchB(0, 0);
    asm volatile("cp.async.commit_group;");
    __syncthreads();

    float acc[2][4][4];
    #pragma unroll
    for (int mi = 0; mi < 2; mi++)
        #pragma unroll
        for (int ni = 0; ni < 4; ni++)
            #pragma unroll
            for (int e = 0; e < 4; e++) acc[mi][ni][e] = 0.f;

    for (int ks = 0; ks < 72; ks++) {
        const int stage = ks & 1;
        if (ks < 71) {
            prefetchB(ks + 1, stage ^ 1);
            asm volatile("cp.async.commit_group;");
            asm volatile("cp.async.wait_group 1;");
        } else {
            asm volatile("cp.async.wait_group 0;");
        }
        __syncthreads();

        const int tap = ks >> 3;
        const int kc  = (ks & 7) << 4;
        const int dy  = tap / 3;
        const int dx  = tap - dy*3;

        uint32_t a_hi[2][4], a_lo[2][4];
        #pragma unroll
        for (int mi = 0; mi < 2; mi++) {
            int p = warpM*32 + mi*16 + (lane & 15);
            int r = ((p >> 3) + dy)*10 + (p & 7) + dx;
            uint32_t off = (uint32_t)(r*A_PITCH_B + (kc + ((lane >> 4) << 3))*2);
            ldsm4(a_hi[mi], aHiU + off);
            ldsm4(a_lo[mi], aLoU + off);
        }

        uint32_t b_hi[4][2], b_lo[4][2];
        const uint32_t bst = bU + stage*8704;
        #pragma unroll
        for (int pair = 0; pair < 2; pair++) {
            uint32_t off = (uint32_t)((lane & 15)*A_PITCH_B +
                           (warpN*32 + pair*16 + ((lane >> 4) << 3))*2);
            uint32_t r4[4];
            ldsm4t(r4, bst + off);
            b_hi[pair*2][0] = r4[0]; b_hi[pair*2][1] = r4[1];
            b_hi[pair*2+1][0] = r4[2]; b_hi[pair*2+1][1] = r4[3];
            ldsm4t(r4, bst + 4352 + off);
            b_lo[pair*2][0] = r4[0]; b_lo[pair*2][1] = r4[1];
            b_lo[pair*2+1][0] = r4[2]; b_lo[pair*2+1][1] = r4[3];
        }

        #pragma unroll
        for (int mi = 0; mi < 2; mi++)
            #pragma unroll
            for (int ni = 0; ni < 4; ni++) {
                mma16816(acc[mi][ni], a_hi[mi], b_hi[ni]);
                mma16816(acc[mi][ni], a_hi[mi], b_lo[ni]);
                mma16816(acc[mi][ni], a_lo[mi], b_hi[ni]);
            }
        __syncthreads();
    }

    #pragma unroll
    for (int mi = 0; mi < 2; mi++) {
        #pragma unroll
        for (int ni = 0; ni < 4; ni++) {
            int p0 = warpM*32 + mi*16 + (lane >> 2);
            int p1 = p0 + 8;
            int ch = warpN*32 + ni*8 + (lane & 3)*2;
            float2 bb = *(const float2*)(bias + ch);
            float v00 = acc[mi][ni][0] + bb.x, v01 = acc[mi][ni][1] + bb.y;
            float v10 = acc[mi][ni][2] + bb.x, v11 = acc[mi][ni][3] + bb.y;
            if (relu) {
                v00 = fmaxf(v00, 0.f); v01 = fmaxf(v01, 0.f);
                v10 = fmaxf(v10, 0.f); v11 = fmaxf(v11, 0.f);
            }
            size_t g0 = (((size_t)b*IMGH + h0 + (p0 >> 3))*IMGW + w0 + (p0 & 7))*CDIM + ch;
            size_t g1 = (((size_t)b*IMGH + h0 + (p1 >> 3))*IMGW + w0 + (p1 & 7))*CDIM + ch;
            if (res) {
                float2 r0 = *(const float2*)(res + g0);
                float2 r1 = *(const float2*)(res + g1);
                v00 += r0.x; v01 += r0.y; v10 += r1.x; v11 += r1.y;
            }
            *(float2*)(out + g0) = make_float2(v00, v01);
            *(float2*)(out + g1) = make_float2(v10, v11);
        }
    }
}

// ================= proj 1x1 (mma) + window_partition -> d_out =================
#define PROJ_SMEM 52224
__global__ __launch_bounds__(256) void proj_mma(
    const float* __restrict__ proj_b, float* __restrict__ out)
{
    extern __shared__ __align__(16) unsigned char smem_raw[];
    __nv_bfloat16* aHiP = reinterpret_cast<__nv_bfloat16*>(smem_raw);
    __nv_bfloat16* aLoP = aHiP + 64*136;
    const uint32_t smem_u = (uint32_t)__cvta_generic_to_shared(smem_raw);
    const uint32_t aHiU = smem_u, aLoU = smem_u + 17408, bU = smem_u + 34816;

    const int t = threadIdx.x, lane = t & 31, wid = t >> 5;
    const int warpM = wid >> 2, warpN = wid & 3;
    const int win = blockIdx.x;
    const int b   = win >> 10;
    const int hw  = (win & 1023) >> 5;
    const int ww  = win & 31;
    const float* img = g_imgA;

    for (int idx = t; idx < 2048; idx += 256) {
        int tok = idx >> 5, c4 = idx & 31;
        int i1 = tok >> 3, j1 = tok & 7;
        size_t pix = (((size_t)b*IMGH + hw*8 + i1)*IMGW + (ww*8 + j1))*CDIM;
        float4 v = *(const float4*)(img + pix + c4*4);
        split_store(aHiP, aLoP, tok*136 + c4*4, v);
    }

    auto prefetchB = [&](int ks, int stage) {
        #pragma unroll
        for (int i = 0; i < 2; i++) {
            int c = t + i*256;
            int part = c >= 256; int cc = c - part*256;
            int row = cc >> 4, seg = cc & 15;
            const __nv_bfloat16* sp = (part ? g_wproj_lo : g_wproj_hi) + (ks*16 + row)*128 + seg*8;
            cp_async16(bU + stage*8704 + part*4352 + row*272 + seg*16, sp);
        }
    };
    prefetchB(0, 0);
    asm volatile("cp.async.commit_group;");
    __syncthreads();

    float acc[2][4][4];
    #pragma unroll
    for (int mi = 0; mi < 2; mi++)
        #pragma unroll
        for (int ni = 0; ni < 4; ni++)
            #pragma unroll
            for (int e = 0; e < 4; e++) acc[mi][ni][e] = 0.f;

    for (int ks = 0; ks < 8; ks++) {
        const int stage = ks & 1;
        if (ks < 7) {
            prefetchB(ks + 1, stage ^ 1);
            asm volatile("cp.async.commit_group;");
            asm volatile("cp.async.wait_group 1;");
        } else {
            asm volatile("cp.async.wait_group 0;");
        }
        __syncthreads();

        const int kc = ks * 16;
        uint32_t a_hi[2][4], a_lo[2][4];
        #pragma unroll
        for (int mi = 0; mi < 2; mi++) {
            int row = warpM*32 + mi*16 + (lane & 15);
            uint32_t off = (uint32_t)(row*272 + (kc + ((lane >> 4) << 3))*2);
            ldsm4(a_hi[mi], aHiU + off);
            ldsm4(a_lo[mi], aLoU + off);
        }
        const uint32_t bst = bU + stage*8704;
        #pragma unroll
        for (int pair = 0; pair < 2; pair++) {
            uint32_t off = (uint32_t)((lane & 15)*272 +
                           (warpN*32 + pair*16 + ((lane >> 4) << 3))*2);
            uint32_t bh[4], bl[4];
            ldsm4t(bh, bst + off);
            ldsm4t(bl, bst + 4352 + off);
            #pragma unroll
            for (int mi = 0; mi < 2; mi++) {
                mma16816(acc[mi][2*pair],   a_hi[mi], bh);
                mma16816(acc[mi][2*pair],   a_hi[mi], bl);
                mma16816(acc[mi][2*pair],   a_lo[mi], bh);
                mma16816(acc[mi][2*pair+1], a_hi[mi], bh+2);
                mma16816(acc[mi][2*pair+1], a_hi[mi], bl+2);
                mma16816(acc[mi][2*pair+1], a_lo[mi], bh+2);
            }
        }
        __syncthreads();
    }

    float* outw = out + (size_t)win * NTOK * CDIM;
    #pragma unroll
    for (int mi = 0; mi < 2; mi++) {
        int row0 = warpM*32 + mi*16 + (lane >> 2);
        int row1 = row0 + 8;
        #pragma unroll
        for (int ni = 0; ni < 4; ni++) {
            int ch = warpN*32 + ni*8 + (lane & 3)*2;
            float2 bb = *(const float2*)(proj_b + ch);
            *(float2*)(outw + row0*128 + ch) =
                make_float2(acc[mi][ni][0] + bb.x, acc[mi][ni][1] + bb.y);
            *(float2*)(outw + row1*128 + ch) =
                make_float2(acc[mi][ni][2] + bb.x, acc[mi][ni][3] + bb.y);
        }
    }
}

// ---------------- launch ----------------
extern "C" void kernel_launch(void* const* d_in, const int* in_sizes, int n_in,
                              void* d_out, int out_size) {
    const float* x         = (const float*)d_in[0];
    const float* ref       = (const float*)d_in[1];
    const float* qkv_w     = (const float*)d_in[2];
    const float* qkv_b     = (const float*)d_in[3];
    const float* proj_w    = (const float*)d_in[4];
    const float* proj_b    = (const float*)d_in[5];
    const float* t11w      = (const float*)d_in[6];
    const float* t11b      = (const float*)d_in[7];
    const float* t12w      = (const float*)d_in[8];
    const float* t12b      = (const float*)d_in[9];
    const float* t21w      = (const float*)d_in[10];
    const float* t21b      = (const float*)d_in[11];
    const float* t22w      = (const float*)d_in[12];
    const float* t22b      = (const float*)d_in[13];
    const float* rel_bias  = (const float*)d_in[14];
    const float* logit_sc  = (const float*)d_in[15];
    const float* gating    = (const float*)d_in[16];
    float* out = (float*)d_out;

    cudaFuncSetAttribute(attn_mma, cudaFuncAttributeMaxDynamicSharedMemorySize,
                         ATTN_SMEM_BYTES);
    cudaFuncSetAttribute(conv3x3_mma, cudaFuncAttributeMaxDynamicSharedMemorySize,
                         CONV_SMEM_BYTES);
    cudaFuncSetAttribute(qkv_mma,  cudaFuncAttributeMaxDynamicSharedMemorySize, QKV_SMEM);
    cudaFuncSetAttribute(kref_mma, cudaFuncAttributeMaxDynamicSharedMemorySize, KREF_SMEM);
    cudaFuncSetAttribute(proj_mma, cudaFuncAttributeMaxDynamicSharedMemorySize, PROJ_SMEM);

    prep_weights<<<192, 256>>>(qkv_w, proj_w);
    split_weights<<<(KCONV*128 + 255)/256, 256>>>(t11w, t12w, t21w, t22w);

    qkv_mma<<<NWIN, 256, QKV_SMEM>>>(x, qkv_b);
    kref_mma<<<NWIN, 256, KREF_SMEM>>>(ref, qkv_b);

    attn_mma<<<NWIN, 256, ATTN_SMEM_BYTES>>>(rel_bias, logit_sc, gating);

    conv3x3_mma<<<NWIN, 256, CONV_SMEM_BYTES>>>(0, 0, t11b, -1, 1, 1);
    conv3x3_mma<<<NWIN, 256, CONV_SMEM_BYTES>>>(1, 1, t12b,  0, 2, 0);
    conv3x3_mma<<<NWIN, 256, CONV_SMEM_BYTES>>>(2, 2, t21b, -1, 1, 1);
    conv3x3_mma<<<NWIN, 256, CONV_SMEM_BYTES>>>(1, 3, t22b,  2, 0, 0);

    proj_mma<<<NWIN, 256, PROJ_SMEM>>>(proj_b, out);
}